// round 12
// baseline (speedup 1.0000x reference)
#include <cuda_runtime.h>
#include <cuda_fp16.h>
#include <cstdint>

// ---------------- problem constants ----------------
#define BS    32
#define SL    2048
#define MEMD  2048                // K of the big GEMM
#define HID   1024                // N of the big GEMM
#define IND   1024
#define MTOT  (BS * SL)           // 65536 GEMM rows (M)
#define OUT_SCORE_OFF (BS * MEMD) // context [32,2048] first, then score [32,2048]

// ---------------- GEMM tiling (fp16) ----------------
#define TM       128
#define TN       256
#define KC       128              // K elems per stage = 2 sub-tiles of 64
#define NKITER   (MEMD / KC)      // 16
#define HALF_A   (TM * 64 * 2)              // 16384 B
#define HALF_B   (TN * 64 * 2)              // 32768 B
#define HALF_BYTES (HALF_A + HALF_B)        // 49152 B
#define STG_BYTES  (2 * HALF_BYTES)         // 98304 B
#define SMEM_GEMM  (2 * STG_BYTES)          // 196608 B (double buffer)

// ---------------- context tiling ----------------
#define SCH   16
#define SROWS (SL / SCH)          // 128

// ---------------- device scratch (static, no allocations) ----------------
__device__ __half g_memh[(long)MTOT * MEMD];   // fp16 copy of memory, written by GEMM nb==0
__device__ __half g_W2Th[HID * MEMD];          // W2 transposed fp16: [h][d], K-major
__device__ float  g_hx[BS * HID];              // x@W1 + b1 + b2
// logit partials: [N-block][wn-warp][row] — one writer per slot, deterministic
__device__ float  g_logitsp[4][4][MTOT];
__device__ float4 g_ctxp[SCH][BS][MEMD / 4];   // context partials, 4 MB

// ---------------- helpers ----------------
__device__ __forceinline__ uint32_t smem_u32(const void* p) {
    uint32_t a;
    asm("{ .reg .u64 t; cvta.to.shared.u64 t, %1; cvt.u32.u64 %0, t; }" : "=r"(a) : "l"(p));
    return a;
}
#define CP_ASYNC16(dst, src) \
    asm volatile("cp.async.cg.shared.global [%0], [%1], 16;" :: "r"(dst), "l"(src) : "memory")
#define CP_COMMIT() asm volatile("cp.async.commit_group;" ::: "memory")
#define CP_WAIT0()  asm volatile("cp.async.wait_group 0;" ::: "memory")

#define STS128V(addr, v) \
    asm volatile("st.shared.v4.b32 [%0], {%1,%2,%3,%4};" \
        :: "r"(addr), "r"((v).x), "r"((v).y), "r"((v).z), "r"((v).w) : "memory")

// ldmatrix x4: four 8x8 b16 tiles (native fp16 use)
#define LDSM4(r, addr) \
    asm volatile("ldmatrix.sync.aligned.m8n8.x4.shared.b16 {%0,%1,%2,%3}, [%4];" \
        : "=r"((r)[0]), "=r"((r)[1]), "=r"((r)[2]), "=r"((r)[3]) : "r"(addr))

// fp16 MMA, fp32 accumulate: m16n8k16
__device__ __forceinline__ void mma_f16(float* c, const uint32_t* a, const uint32_t* b) {
    asm volatile(
        "mma.sync.aligned.m16n8k16.row.col.f32.f16.f16.f32 "
        "{%0,%1,%2,%3}, {%4,%5,%6,%7}, {%8,%9}, {%0,%1,%2,%3};"
        : "+f"(c[0]), "+f"(c[1]), "+f"(c[2]), "+f"(c[3])
        : "r"(a[0]), "r"(a[1]), "r"(a[2]), "r"(a[3]), "r"(b[0]), "r"(b[1]));
}

__device__ __forceinline__ float fast_tanh(float x) {
    float t; asm("tanh.approx.f32 %0, %1;" : "=f"(t) : "f"(x));
    return t;
}

__device__ __forceinline__ uint32_t pack_h2(float a, float b) {
    __half2 h = __floats2half2_rn(a, b);
    return *(uint32_t*)&h;
}

// ============================================================
// B loader: B [256 x 64] fp16 per half, both halves of one stage, cp.async
// row layout: 8 chunks of 16 B, chunk index XOR (row & 7)
// ============================================================
__device__ __forceinline__ void load_b_stage(
    int tid, uint32_t st, const __half* __restrict__ Bg)
{
    #pragma unroll
    for (int h = 0; h < 2; h++) {
        uint32_t base = st + (uint32_t)h * HALF_BYTES + HALF_A;
        const __half* src = Bg + h * 64;
        #pragma unroll
        for (int o = tid; o < TN * 8; o += 256) {
            int r = o >> 3, ch = o & 7;
            uint32_t dst = base + (uint32_t)(r * 128 + ((ch ^ (r & 7)) << 4));
            CP_ASYNC16(dst, src + (long)r * MEMD + ch * 8);
        }
    }
}

// ============================================================
// GEMM (memory @ W2T, fp16 -> fp32) fused with tanh/v-dot -> logit partials.
// A path: reads fp32 memory directly, converts inline to fp16 smem tiles
// (and nb==0 CTAs stream the fp16 copy to g_memh for the context kernel).
// grid (HID/TN = 4, MTOT/TM = 512), 256 threads, warp tile 64x64
// ============================================================
__global__ void __launch_bounds__(256, 1) gemm_score_kernel(
    const float* __restrict__ mem32, const float* __restrict__ v)
{
    extern __shared__ float dsm[];
    __shared__ float hxs[TN], vt[TN];

    const int tid  = threadIdx.x;
    const int wid  = tid >> 5, lane = tid & 31;
    const int wm   = wid >> 2, wn = wid & 3;       // 2 x 4 warp grid
    const int tg   = lane >> 2, tig = lane & 3;
    const int  nb  = blockIdx.x;                   // N-block id (0..3)
    const int  n0  = nb * TN;                      // global h base
    const long g0  = (long)blockIdx.y * TM;        // global row base
    const int  b   = blockIdx.y >> 4;              // SL/TM = 16 M-tiles per batch

    if (tid < TN) {
        hxs[tid] = g_hx[b * HID + n0 + tid];
        vt[tid]  = v[n0 + tid];
    }

    const uint32_t sbase = smem_u32(dsm);
    const float*  Am = mem32 + g0 * MEMD;          // fp32 A source
    __half*       Agh = g_memh + g0 * MEMD;        // fp16 A sink (nb==0 only)
    const __half* Bg  = g_W2Th + (long)n0 * MEMD;

    // A-conversion chunk geometry: per stage, thread handles 8 chunks of 8 halves,
    // chunk id (q = step&3): o = tid + q*256 within a 1024-chunk half.
    int      aoff[4];          // element offset within a K-half: r*MEMD + ch*8
    uint32_t ssw[4];           // swizzled smem byte offset: r*128 + ((ch^r&7)<<4)
    #pragma unroll
    for (int q = 0; q < 4; q++) {
        int o = tid + q * 256, r = o >> 3, ch = o & 7;
        aoff[q] = r * MEMD + ch * 8;
        ssw[q]  = (uint32_t)(r * 128 + ((ch ^ (r & 7)) << 4));
    }

    // ldmatrix per-thread address pieces (identical per 64-K half)
    const int lane7 = lane & 7;
    const uint32_t rowA0 = (uint32_t)((wm * 64 + ((lane >> 3) & 1) * 8 + lane7) * 128);
    const uint32_t rowB0 = (uint32_t)((wn * 64 + ((lane >> 4) & 1) * 8 + lane7) * 128);
    const int cbA = (lane >> 4) & 1, cbB = (lane >> 3) & 1;
    uint32_t ofsA[4], ofsB[4];
    #pragma unroll
    for (int ks = 0; ks < 4; ks++) {
        ofsA[ks] = (uint32_t)(((2 * ks + cbA) ^ lane7) << 4);
        ofsB[ks] = (uint32_t)(((2 * ks + cbB) ^ lane7) << 4);
    }

    float acc[4][8][4];
    #pragma unroll
    for (int i = 0; i < 4; i++)
        #pragma unroll
        for (int j = 0; j < 8; j++)
            #pragma unroll
            for (int k = 0; k < 4; k++) acc[i][j][k] = 0.f;

    // ---- prologue: B stage 0 via cp.async; A stage 0 converted straight-line
    load_b_stage(tid, sbase, Bg);
    CP_COMMIT();
    #pragma unroll
    for (int s = 0; s < 8; s++) {
        const int q = s & 3, h = s >> 2;
        const long off = (long)aoff[q] + h * 64;
        const float4* p = (const float4*)(Am + off);
        float4 f0 = p[0], f1 = p[1];
        uint4 vv;
        vv.x = pack_h2(f0.x, f0.y); vv.y = pack_h2(f0.z, f0.w);
        vv.z = pack_h2(f1.x, f1.y); vv.w = pack_h2(f1.z, f1.w);
        STS128V(sbase + (uint32_t)h * HALF_BYTES + ssw[q], vv);
        if (nb == 0) *(uint4*)(Agh + off) = vv;
    }

    for (int it = 0; it < NKITER; it++) {
        CP_WAIT0();
        __syncthreads();

        const int prep = (it + 1 < NKITER);
        const uint32_t nstg = sbase + (uint32_t)((it + 1) & 1) * STG_BYTES;
        const float*  Ams = Am  + (it + 1) * KC;   // next-stage fp32 A
        __half*       Ags = Agh + (it + 1) * KC;
        if (prep) {
            load_b_stage(tid, nstg, Bg + (it + 1) * KC);
            CP_COMMIT();
        }

        const uint32_t stg = sbase + (uint32_t)(it & 1) * STG_BYTES;
        float4 f0, f1;
        if (prep) {   // LDG for step 0 of next stage's A conversion
            const float4* p = (const float4*)(Ams + aoff[0]);
            f0 = p[0]; f1 = p[1];
        }

        #pragma unroll
        for (int s = 0; s < 8; s++) {
            const int h = s >> 2, ks = s & 3;
            const uint32_t sA = stg + (uint32_t)h * HALF_BYTES;
            const uint32_t sB = sA + HALF_A;
            uint32_t a[4][4], bf[4][4];
            #pragma unroll
            for (int mi = 0; mi < 4; mi++)
                LDSM4(a[mi], sA + rowA0 + (uint32_t)(mi * 2048) + ofsA[ks]);
            #pragma unroll
            for (int p = 0; p < 4; p++)
                LDSM4(bf[p], sB + rowB0 + (uint32_t)(p * 2048) + ofsB[ks]);

            if (prep) {   // consume LDG(s): cvt + STS (+STG), then issue LDG(s+1)
                uint4 vv;
                vv.x = pack_h2(f0.x, f0.y); vv.y = pack_h2(f0.z, f0.w);
                vv.z = pack_h2(f1.x, f1.y); vv.w = pack_h2(f1.z, f1.w);
                const long off = (long)aoff[s & 3] + (s >> 2) * 64;
                STS128V(nstg + (uint32_t)(s >> 2) * HALF_BYTES + ssw[s & 3], vv);
                if (nb == 0) *(uint4*)(Ags + off) = vv;
                if (s < 7) {
                    const long noff = (long)aoff[(s + 1) & 3] + ((s + 1) >> 2) * 64;
                    const float4* p = (const float4*)(Ams + noff);
                    f0 = p[0]; f1 = p[1];
                }
            }

            #pragma unroll
            for (int mi = 0; mi < 4; mi++)
                #pragma unroll
                for (int p = 0; p < 4; p++) {
                    mma_f16(acc[mi][2 * p],     a[mi], &bf[p][0]);
                    mma_f16(acc[mi][2 * p + 1], a[mi], &bf[p][2]);
                }
        }
    }
    __syncthreads();

    // Epilogue: partial logit over this warp's 64 h-columns; one writer per
    // (nb, wn, row) slot -> plain store, race-free, deterministic.
    #pragma unroll
    for (int mi = 0; mi < 4; mi++) {
        float p0 = 0.f, p1 = 0.f;
        #pragma unroll
        for (int ni = 0; ni < 8; ni++) {
            int col = wn * 64 + ni * 8 + tig * 2;
            float v0 = vt[col], v1 = vt[col + 1];
            float h0 = hxs[col], h1 = hxs[col + 1];
            p0 += v0 * fast_tanh(h0 + acc[mi][ni][0]) + v1 * fast_tanh(h1 + acc[mi][ni][1]);
            p1 += v0 * fast_tanh(h0 + acc[mi][ni][2]) + v1 * fast_tanh(h1 + acc[mi][ni][3]);
        }
        p0 += __shfl_xor_sync(0xFFFFFFFFu, p0, 1);
        p0 += __shfl_xor_sync(0xFFFFFFFFu, p0, 2);
        p1 += __shfl_xor_sync(0xFFFFFFFFu, p1, 1);
        p1 += __shfl_xor_sync(0xFFFFFFFFu, p1, 2);
        if (tig == 0) {
            long r = g0 + wm * 64 + mi * 16 + tg;
            g_logitsp[nb][wn][r]     = p0;
            g_logitsp[nb][wn][r + 8] = p1;
        }
    }
}

// ============================================================
// Small kernels
// ============================================================
__global__ void transpose_w2_kernel(const float* __restrict__ W2) {
    __shared__ float t[32][33];
    int d0 = blockIdx.x * 32, h0 = blockIdx.y * 32;
    int tx = threadIdx.x, ty = threadIdx.y;
    #pragma unroll
    for (int i = 0; i < 32; i += 8)
        t[ty + i][tx] = W2[(long)(d0 + ty + i) * HID + h0 + tx];
    __syncthreads();
    #pragma unroll
    for (int i = 0; i < 32; i += 8)
        g_W2Th[(long)(h0 + ty + i) * MEMD + d0 + tx] = __float2half(t[tx][ty + i]);
}

__global__ void __launch_bounds__(256) hx_kernel(
    const float* __restrict__ x, const float* __restrict__ W1,
    const float* __restrict__ b1, const float* __restrict__ b2)
{
    int h = blockIdx.x * 256 + threadIdx.x;
    int b = blockIdx.y;
    const float* xr = x + b * IND;
    float acc = 0.f;
    #pragma unroll 8
    for (int d = 0; d < IND; d++)
        acc += xr[d] * W1[(long)d * HID + h];
    g_hx[b * HID + h] = acc + b1[h] + b2[h];
}

__global__ void __launch_bounds__(256) softmax_kernel(float* __restrict__ out) {
    __shared__ float buf[SL];
    __shared__ float red[256];
    const int b = blockIdx.x, tid = threadIdx.x;
    const float* lp = &g_logitsp[0][0][0];
    float m = -1e30f;
    for (int s = tid; s < SL; s += 256) {
        int i = b * SL + s;
        float l = 0.f;
        #pragma unroll
        for (int j = 0; j < 16; j++)
            l += lp[j * MTOT + i];
        buf[s] = l;
        m = fmaxf(m, l);
    }
    red[tid] = m; __syncthreads();
    for (int o = 128; o > 0; o >>= 1) {
        if (tid < o) red[tid] = fmaxf(red[tid], red[tid + o]);
        __syncthreads();
    }
    m = red[0]; __syncthreads();
    float sum = 0.f;
    for (int s = tid; s < SL; s += 256) {
        float e = __expf(buf[s] - m);
        buf[s] = e;
        sum += e;
    }
    red[tid] = sum; __syncthreads();
    for (int o = 128; o > 0; o >>= 1) {
        if (tid < o) red[tid] += red[tid + o];
        __syncthreads();
    }
    float inv = 1.f / red[0];
    for (int s = tid; s < SL; s += 256)
        out[OUT_SCORE_OFF + b * SL + s] = buf[s] * inv;
}

// context partials from the fp16 memory copy: grid (SCH, BS), 256 threads.
__global__ void __launch_bounds__(256) context_partial_kernel(const float* __restrict__ out)
{
    const int sc = blockIdx.x, b = blockIdx.y;
    const int d8 = threadIdx.x;                       // 0..255
    const float* sp = out + OUT_SCORE_OFF + b * SL + sc * SROWS;
    const uint4* mb = (const uint4*)(g_memh + ((long)b * SL + sc * SROWS) * MEMD) + d8;
    float a0[8] = {0,0,0,0,0,0,0,0}, a1[8] = {0,0,0,0,0,0,0,0};
    #pragma unroll 2
    for (int s = 0; s < SROWS; s += 2) {
        float w0 = sp[s], w1 = sp[s + 1];
        uint4 v0 = mb[(long)s * (MEMD / 8)];
        uint4 v1 = mb[(long)(s + 1) * (MEMD / 8)];
        float2 f;
        f = __half22float2(*(__half2*)&v0.x); a0[0] += w0 * f.x; a0[1] += w0 * f.y;
        f = __half22float2(*(__half2*)&v0.y); a0[2] += w0 * f.x; a0[3] += w0 * f.y;
        f = __half22float2(*(__half2*)&v0.z); a0[4] += w0 * f.x; a0[5] += w0 * f.y;
        f = __half22float2(*(__half2*)&v0.w); a0[6] += w0 * f.x; a0[7] += w0 * f.y;
        f = __half22float2(*(__half2*)&v1.x); a1[0] += w1 * f.x; a1[1] += w1 * f.y;
        f = __half22float2(*(__half2*)&v1.y); a1[2] += w1 * f.x; a1[3] += w1 * f.y;
        f = __half22float2(*(__half2*)&v1.z); a1[4] += w1 * f.x; a1[5] += w1 * f.y;
        f = __half22float2(*(__half2*)&v1.w); a1[6] += w1 * f.x; a1[7] += w1 * f.y;
    }
    float4* dst = &g_ctxp[sc][b][2 * d8];
    dst[0] = make_float4(a0[0] + a1[0], a0[1] + a1[1], a0[2] + a1[2], a0[3] + a1[3]);
    dst[1] = make_float4(a0[4] + a1[4], a0[5] + a1[5], a0[6] + a1[6], a0[7] + a1[7]);
}

__global__ void __launch_bounds__(256) ctx_reduce_kernel(float* __restrict__ out) {
    const int i  = blockIdx.x * 256 + threadIdx.x;    // 0..16383 float4 slots
    const int b  = i / (MEMD / 4), d4 = i % (MEMD / 4);
    float4 s = make_float4(0.f, 0.f, 0.f, 0.f);
    #pragma unroll
    for (int c = 0; c < SCH; c++) {
        float4 p = g_ctxp[c][b][d4];
        s.x += p.x; s.y += p.y; s.z += p.z; s.w += p.w;
    }
    ((float4*)out)[i] = s;
}

// ============================================================
// Launch
// ============================================================
extern "C" void kernel_launch(void* const* d_in, const int* in_sizes, int n_in,
                              void* d_out, int out_size)
{
    const float* x      = (const float*)d_in[0];
    const float* memory = (const float*)d_in[1];
    const float* W1     = (const float*)d_in[2];
    const float* b1     = (const float*)d_in[3];
    const float* W2     = (const float*)d_in[4];
    const float* b2     = (const float*)d_in[5];
    const float* v      = (const float*)d_in[6];
    // d_in[7] = bv: cancels under softmax (shift invariance), unused.
    float* out = (float*)d_out;

    cudaFuncSetAttribute(gemm_score_kernel,
                         cudaFuncAttributeMaxDynamicSharedMemorySize, SMEM_GEMM);

    transpose_w2_kernel<<<dim3(MEMD / 32, HID / 32), dim3(32, 8)>>>(W2);
    hx_kernel<<<dim3(HID / 256, BS), 256>>>(x, W1, b1, b2);
    gemm_score_kernel<<<dim3(HID / TN, MTOT / TM), 256, SMEM_GEMM>>>(memory, v);
    softmax_kernel<<<BS, 256>>>(out);
    context_partial_kernel<<<dim3(SCH, BS), 256>>>(out);
    ctx_reduce_kernel<<<BS * MEMD / 4 / 256, 256>>>(out);
}

// round 13
// speedup vs baseline: 1.4614x; 1.4614x over previous
#include <cuda_runtime.h>
#include <cuda_fp16.h>
#include <cstdint>

// ---------------- problem constants ----------------
#define BS    32
#define SL    2048
#define MEMD  2048                // K of the big GEMM
#define HID   1024                // N of the big GEMM
#define IND   1024
#define MTOT  (BS * SL)           // 65536 GEMM rows (M)
#define OUT_SCORE_OFF (BS * MEMD) // context [32,2048] first, then score [32,2048]

// ---------------- GEMM tiling (fp16) ----------------
#define TM       128
#define TN       256
#define KC       128              // K elems per stage = 2 sub-tiles of 64
#define NKITER   (MEMD / KC)      // 16
#define HALF_A   (TM * 64 * 2)              // 16384 B
#define HALF_B   (TN * 64 * 2)              // 32768 B
#define HALF_BYTES (HALF_A + HALF_B)        // 49152 B
#define STG_BYTES  (2 * HALF_BYTES)         // 98304 B
#define SMEM_GEMM  (2 * STG_BYTES)          // 196608 B (double buffer)

// ---------------- context tiling ----------------
#define SCH   16
#define SROWS (SL / SCH)          // 128

// ---------------- prep kernel grid partition ----------------
#define PREP_CONV_CTAS  65536     // memory fp32->fp16: 256 thr x 8 elems = 2048/CTA
#define PREP_TRAN_CTAS  2048      // W2 transpose: (MEMD/32)*(HID/32)
#define PREP_HX_CTAS    128       // hx: (HID/256)*BS

// ---------------- device scratch (static, no allocations) ----------------
__device__ __half g_memh[(long)MTOT * MEMD];   // fp16 copy of memory (256 MB, bss)
__device__ __half g_W2Th[HID * MEMD];          // W2 transposed fp16: [h][d], K-major
__device__ float  g_hx[BS * HID];              // x@W1 + b1 + b2
// logit partials: [N-block][wn-warp][row] — one writer per slot, deterministic
__device__ float  g_logitsp[4][4][MTOT];
__device__ float4 g_ctxp[SCH][BS][MEMD / 4];   // context partials, 4 MB

// ---------------- helpers ----------------
__device__ __forceinline__ uint32_t smem_u32(const void* p) {
    uint32_t a;
    asm("{ .reg .u64 t; cvta.to.shared.u64 t, %1; cvt.u32.u64 %0, t; }" : "=r"(a) : "l"(p));
    return a;
}
#define CP_ASYNC16(dst, src) \
    asm volatile("cp.async.cg.shared.global [%0], [%1], 16;" :: "r"(dst), "l"(src) : "memory")
#define CP_COMMIT() asm volatile("cp.async.commit_group;" ::: "memory")
#define CP_WAIT0()  asm volatile("cp.async.wait_group 0;" ::: "memory")

// ldmatrix x4: four 8x8 b16 tiles (native fp16 use)
#define LDSM4(r, addr) \
    asm volatile("ldmatrix.sync.aligned.m8n8.x4.shared.b16 {%0,%1,%2,%3}, [%4];" \
        : "=r"((r)[0]), "=r"((r)[1]), "=r"((r)[2]), "=r"((r)[3]) : "r"(addr))

// fp16 MMA, fp32 accumulate: m16n8k16
__device__ __forceinline__ void mma_f16(float* c, const uint32_t* a, const uint32_t* b) {
    asm volatile(
        "mma.sync.aligned.m16n8k16.row.col.f32.f16.f16.f32 "
        "{%0,%1,%2,%3}, {%4,%5,%6,%7}, {%8,%9}, {%0,%1,%2,%3};"
        : "+f"(c[0]), "+f"(c[1]), "+f"(c[2]), "+f"(c[3])
        : "r"(a[0]), "r"(a[1]), "r"(a[2]), "r"(a[3]), "r"(b[0]), "r"(b[1]));
}

__device__ __forceinline__ float fast_tanh(float x) {
    float t; asm("tanh.approx.f32 %0, %1;" : "=f"(t) : "f"(x));
    return t;
}

__device__ __forceinline__ uint32_t pack_h2(float a, float b) {
    __half2 h = __floats2half2_rn(a, b);
    return *(uint32_t*)&h;
}

// ============================================================
// Prep kernel: one launch, three independent jobs partitioned by blockIdx.x.
//   [0, 65536)                 : memory fp32 -> fp16 (768 MB stream)
//   [65536, 65536+2048)        : W2 transpose -> fp16 K-major
//   [65536+2048, +128)         : hx = x@W1 + b1 + b2
// The small jobs ride inside the convert's memory-bound wave structure.
// ============================================================
__global__ void __launch_bounds__(256) prep_kernel(
    const float4* __restrict__ mem4, const float* __restrict__ W2,
    const float* __restrict__ x, const float* __restrict__ W1,
    const float* __restrict__ b1, const float* __restrict__ b2)
{
    const int cta = blockIdx.x;
    const int tid = threadIdx.x;

    if (cta < PREP_CONV_CTAS) {
        // ---- memory fp32 -> fp16: each thread converts 8 floats ----
        long i = (long)cta * 256 + tid;            // uint4 slot
        float4 f0 = mem4[2 * i], f1 = mem4[2 * i + 1];
        uint4 v;
        v.x = pack_h2(f0.x, f0.y);
        v.y = pack_h2(f0.z, f0.w);
        v.z = pack_h2(f1.x, f1.y);
        v.w = pack_h2(f1.z, f1.w);
        ((uint4*)g_memh)[i] = v;
    } else if (cta < PREP_CONV_CTAS + PREP_TRAN_CTAS) {
        // ---- W2 transpose: 32x32 tile per CTA, threads act as (32, 8) ----
        __shared__ float t[32][33];
        const int c  = cta - PREP_CONV_CTAS;
        const int d0 = (c % (MEMD / 32)) * 32;
        const int h0 = (c / (MEMD / 32)) * 32;
        const int tx = tid & 31, ty = tid >> 5;
        #pragma unroll
        for (int i = 0; i < 32; i += 8)
            t[ty + i][tx] = W2[(long)(d0 + ty + i) * HID + h0 + tx];
        __syncthreads();
        #pragma unroll
        for (int i = 0; i < 32; i += 8)
            g_W2Th[(long)(h0 + ty + i) * MEMD + d0 + tx] = __float2half(t[tx][ty + i]);
    } else {
        // ---- hx: h = x@W1 + b1 + b2 ----
        const int c = cta - PREP_CONV_CTAS - PREP_TRAN_CTAS;   // 0..127
        const int h = (c & 3) * 256 + tid;
        const int b = c >> 2;
        const float* xr = x + b * IND;
        float acc = 0.f;
        #pragma unroll 8
        for (int d = 0; d < IND; d++)
            acc += xr[d] * W1[(long)d * HID + h];
        g_hx[b * HID + h] = acc + b1[h] + b2[h];
    }
}

// ============================================================
// Half-stage loader: A [128 x 64] + B [256 x 64] fp16, 128-B rows, swizzled
// row layout: 8 chunks of 16 B (8 fp16), chunk index XOR (row & 7)
// ============================================================
__device__ __forceinline__ void load_half(
    int tid, uint32_t st,
    const __half* __restrict__ Ag, const __half* __restrict__ Bg)
{
    #pragma unroll
    for (int o = tid; o < TM * 8; o += 256) {
        int r = o >> 3, ch = o & 7;
        uint32_t dst = st + (uint32_t)(r * 128 + ((ch ^ (r & 7)) << 4));
        CP_ASYNC16(dst, Ag + (long)r * MEMD + ch * 8);
    }
    #pragma unroll
    for (int o = tid; o < TN * 8; o += 256) {
        int r = o >> 3, ch = o & 7;
        uint32_t dst = st + HALF_A + (uint32_t)(r * 128 + ((ch ^ (r & 7)) << 4));
        CP_ASYNC16(dst, Bg + (long)r * MEMD + ch * 8);
    }
}

// ============================================================
// GEMM (memory @ W2T, fp16 -> fp32) fused with tanh/v-dot -> logit partials
// grid (HID/TN = 4, MTOT/TM = 512), 256 threads, warp tile 64x64
// ============================================================
__global__ void __launch_bounds__(256, 1) gemm_score_kernel(const float* __restrict__ v)
{
    extern __shared__ float dsm[];
    __shared__ float hxs[TN], vt[TN];

    const int tid  = threadIdx.x;
    const int wid  = tid >> 5, lane = tid & 31;
    const int wm   = wid >> 2, wn = wid & 3;       // 2 x 4 warp grid
    const int tg   = lane >> 2, tig = lane & 3;
    const int  nb  = blockIdx.x;                   // N-block id (0..3)
    const int  n0  = nb * TN;                      // global h base
    const long g0  = (long)blockIdx.y * TM;        // global row base
    const int  b   = blockIdx.y >> 4;              // SL/TM = 16 M-tiles per batch

    if (tid < TN) {
        hxs[tid] = g_hx[b * HID + n0 + tid];
        vt[tid]  = v[n0 + tid];
    }

    const uint32_t sbase = smem_u32(dsm);
    const __half* Ag = g_memh + g0 * MEMD;
    const __half* Bg = g_W2Th + (long)n0 * MEMD;

    // ldmatrix per-thread address pieces (identical per 64-K half)
    const int lane7 = lane & 7;
    const uint32_t rowA0 = (uint32_t)((wm * 64 + ((lane >> 3) & 1) * 8 + lane7) * 128);
    const uint32_t rowB0 = (uint32_t)((wn * 64 + ((lane >> 4) & 1) * 8 + lane7) * 128);
    const int cbA = (lane >> 4) & 1, cbB = (lane >> 3) & 1;
    uint32_t ofsA[4], ofsB[4];
    #pragma unroll
    for (int ks = 0; ks < 4; ks++) {               // 4 k16-steps per 64-K half
        ofsA[ks] = (uint32_t)(((2 * ks + cbA) ^ lane7) << 4);
        ofsB[ks] = (uint32_t)(((2 * ks + cbB) ^ lane7) << 4);
    }

    float acc[4][8][4];
    #pragma unroll
    for (int i = 0; i < 4; i++)
        #pragma unroll
        for (int j = 0; j < 8; j++)
            #pragma unroll
            for (int k = 0; k < 4; k++) acc[i][j][k] = 0.f;

    // prologue: stage 0 (both halves)
    load_half(tid, sbase,              Ag,      Bg);
    load_half(tid, sbase + HALF_BYTES, Ag + 64, Bg + 64);
    CP_COMMIT();

    for (int it = 0; it < NKITER; it++) {
        CP_WAIT0();
        __syncthreads();

        if (it + 1 < NKITER) {    // prefetch next stage into the other buffer
            uint32_t st = sbase + (uint32_t)((it + 1) & 1) * STG_BYTES;
            const __half* Ain = Ag + (it + 1) * KC;
            const __half* Bin = Bg + (it + 1) * KC;
            load_half(tid, st,              Ain,      Bin);
            load_half(tid, st + HALF_BYTES, Ain + 64, Bin + 64);
            CP_COMMIT();
        }

        const uint32_t stg = sbase + (uint32_t)(it & 1) * STG_BYTES;
        #pragma unroll
        for (int h = 0; h < 2; h++) {
            const uint32_t sA = stg + (uint32_t)h * HALF_BYTES;
            const uint32_t sB = sA + HALF_A;
            #pragma unroll
            for (int ks = 0; ks < 4; ks++) {       // each ks consumes K=16
                uint32_t a[4][4], bf[4][4];
                #pragma unroll
                for (int mi = 0; mi < 4; mi++)
                    LDSM4(a[mi], sA + rowA0 + (uint32_t)(mi * 2048) + ofsA[ks]);
                #pragma unroll
                for (int p = 0; p < 4; p++)        // each covers n16
                    LDSM4(bf[p], sB + rowB0 + (uint32_t)(p * 2048) + ofsB[ks]);
                #pragma unroll
                for (int mi = 0; mi < 4; mi++)
                    #pragma unroll
                    for (int p = 0; p < 4; p++) {
                        mma_f16(acc[mi][2 * p],     a[mi], &bf[p][0]);
                        mma_f16(acc[mi][2 * p + 1], a[mi], &bf[p][2]);
                    }
            }
        }
    }
    __syncthreads();

    // Epilogue: partial logit over this warp's 64 h-columns; one writer per
    // (nb, wn, row) slot -> plain store, race-free, deterministic.
    #pragma unroll
    for (int mi = 0; mi < 4; mi++) {
        float p0 = 0.f, p1 = 0.f;
        #pragma unroll
        for (int ni = 0; ni < 8; ni++) {
            int col = wn * 64 + ni * 8 + tig * 2;
            float v0 = vt[col], v1 = vt[col + 1];
            float h0 = hxs[col], h1 = hxs[col + 1];
            p0 += v0 * fast_tanh(h0 + acc[mi][ni][0]) + v1 * fast_tanh(h1 + acc[mi][ni][1]);
            p1 += v0 * fast_tanh(h0 + acc[mi][ni][2]) + v1 * fast_tanh(h1 + acc[mi][ni][3]);
        }
        p0 += __shfl_xor_sync(0xFFFFFFFFu, p0, 1);
        p0 += __shfl_xor_sync(0xFFFFFFFFu, p0, 2);
        p1 += __shfl_xor_sync(0xFFFFFFFFu, p1, 1);
        p1 += __shfl_xor_sync(0xFFFFFFFFu, p1, 2);
        if (tig == 0) {
            long r = g0 + wm * 64 + mi * 16 + tg;
            g_logitsp[nb][wn][r]     = p0;
            g_logitsp[nb][wn][r + 8] = p1;
        }
    }
}

// ============================================================
// Softmax over summed logit partials
// ============================================================
__global__ void __launch_bounds__(256) softmax_kernel(float* __restrict__ out) {
    __shared__ float buf[SL];
    __shared__ float red[256];
    const int b = blockIdx.x, tid = threadIdx.x;
    const float* lp = &g_logitsp[0][0][0];
    float m = -1e30f;
    for (int s = tid; s < SL; s += 256) {
        int i = b * SL + s;
        float l = 0.f;
        #pragma unroll
        for (int j = 0; j < 16; j++)
            l += lp[j * MTOT + i];
        buf[s] = l;
        m = fmaxf(m, l);
    }
    red[tid] = m; __syncthreads();
    for (int o = 128; o > 0; o >>= 1) {
        if (tid < o) red[tid] = fmaxf(red[tid], red[tid + o]);
        __syncthreads();
    }
    m = red[0]; __syncthreads();
    float sum = 0.f;
    for (int s = tid; s < SL; s += 256) {
        float e = __expf(buf[s] - m);
        buf[s] = e;
        sum += e;
    }
    red[tid] = sum; __syncthreads();
    for (int o = 128; o > 0; o >>= 1) {
        if (tid < o) red[tid] += red[tid + o];
        __syncthreads();
    }
    float inv = 1.f / red[0];
    for (int s = tid; s < SL; s += 256)
        out[OUT_SCORE_OFF + b * SL + s] = buf[s] * inv;
}

// ============================================================
// Context partials from the fp16 memory copy: grid (SCH, BS), 256 threads.
// Each thread accumulates 8 d-columns (one uint4 = 8 halves per row).
// ============================================================
__global__ void __launch_bounds__(256) context_partial_kernel(const float* __restrict__ out)
{
    const int sc = blockIdx.x, b = blockIdx.y;
    const int d8 = threadIdx.x;                       // 0..255
    const float* sp = out + OUT_SCORE_OFF + b * SL + sc * SROWS;
    const uint4* mb = (const uint4*)(g_memh + ((long)b * SL + sc * SROWS) * MEMD) + d8;
    float a0[8] = {0,0,0,0,0,0,0,0}, a1[8] = {0,0,0,0,0,0,0,0};
    #pragma unroll 2
    for (int s = 0; s < SROWS; s += 2) {
        float w0 = sp[s], w1 = sp[s + 1];
        uint4 v0 = mb[(long)s * (MEMD / 8)];
        uint4 v1 = mb[(long)(s + 1) * (MEMD / 8)];
        float2 f;
        f = __half22float2(*(__half2*)&v0.x); a0[0] += w0 * f.x; a0[1] += w0 * f.y;
        f = __half22float2(*(__half2*)&v0.y); a0[2] += w0 * f.x; a0[3] += w0 * f.y;
        f = __half22float2(*(__half2*)&v0.z); a0[4] += w0 * f.x; a0[5] += w0 * f.y;
        f = __half22float2(*(__half2*)&v0.w); a0[6] += w0 * f.x; a0[7] += w0 * f.y;
        f = __half22float2(*(__half2*)&v1.x); a1[0] += w1 * f.x; a1[1] += w1 * f.y;
        f = __half22float2(*(__half2*)&v1.y); a1[2] += w1 * f.x; a1[3] += w1 * f.y;
        f = __half22float2(*(__half2*)&v1.z); a1[4] += w1 * f.x; a1[5] += w1 * f.y;
        f = __half22float2(*(__half2*)&v1.w); a1[6] += w1 * f.x; a1[7] += w1 * f.y;
    }
    float4* dst = &g_ctxp[sc][b][2 * d8];
    dst[0] = make_float4(a0[0] + a1[0], a0[1] + a1[1], a0[2] + a1[2], a0[3] + a1[3]);
    dst[1] = make_float4(a0[4] + a1[4], a0[5] + a1[5], a0[6] + a1[6], a0[7] + a1[7]);
}

__global__ void __launch_bounds__(256) ctx_reduce_kernel(float* __restrict__ out) {
    const int i  = blockIdx.x * 256 + threadIdx.x;    // 0..16383 float4 slots
    const int b  = i / (MEMD / 4), d4 = i % (MEMD / 4);
    float4 s = make_float4(0.f, 0.f, 0.f, 0.f);
    #pragma unroll
    for (int c = 0; c < SCH; c++) {
        float4 p = g_ctxp[c][b][d4];
        s.x += p.x; s.y += p.y; s.z += p.z; s.w += p.w;
    }
    ((float4*)out)[i] = s;
}

// ============================================================
// Launch
// ============================================================
extern "C" void kernel_launch(void* const* d_in, const int* in_sizes, int n_in,
                              void* d_out, int out_size)
{
    const float* x      = (const float*)d_in[0];
    const float* memory = (const float*)d_in[1];
    const float* W1     = (const float*)d_in[2];
    const float* b1     = (const float*)d_in[3];
    const float* W2     = (const float*)d_in[4];
    const float* b2     = (const float*)d_in[5];
    const float* v      = (const float*)d_in[6];
    // d_in[7] = bv: cancels under softmax (shift invariance), unused.
    float* out = (float*)d_out;

    cudaFuncSetAttribute(gemm_score_kernel,
                         cudaFuncAttributeMaxDynamicSharedMemorySize, SMEM_GEMM);

    prep_kernel<<<PREP_CONV_CTAS + PREP_TRAN_CTAS + PREP_HX_CTAS, 256>>>(
        (const float4*)memory, W2, x, W1, b1, b2);
    gemm_score_kernel<<<dim3(HID / TN, MTOT / TM), 256, SMEM_GEMM>>>(v);
    softmax_kernel<<<BS, 256>>>(out);
    context_partial_kernel<<<dim3(SCH, BS), 256>>>(out);
    ctx_reduce_kernel<<<BS * MEMD / 4 / 256, 256>>>(out);
}

// round 14
// speedup vs baseline: 1.5328x; 1.0488x over previous
#include <cuda_runtime.h>
#include <cuda_fp16.h>
#include <cstdint>

// ---------------- problem constants ----------------
#define BS    32
#define SL    2048
#define MEMD  2048                // K of the big GEMM
#define HID   1024                // N of the big GEMM
#define IND   1024
#define MTOT  (BS * SL)           // 65536 GEMM rows (M)
#define OUT_SCORE_OFF (BS * MEMD) // context [32,2048] first, then score [32,2048]

// ---------------- GEMM tiling (fp16) ----------------
#define TM       128
#define TN       256
#define KC       128              // K elems per stage = 2 sub-tiles of 64
#define NKITER   (MEMD / KC)      // 16
#define HALF_A   (TM * 64 * 2)              // 16384 B
#define HALF_B   (TN * 64 * 2)              // 32768 B
#define HALF_BYTES (HALF_A + HALF_B)        // 49152 B
#define STG_BYTES  (2 * HALF_BYTES)         // 98304 B
#define SMEM_GEMM  (2 * STG_BYTES)          // 196608 B (double buffer)

// ---------------- context tiling ----------------
#define SCH   16
#define SROWS (SL / SCH)          // 128

// ---------------- prep kernel grid partition (compute jobs FIRST) ----------------
#define PREP_TRAN_CTAS  2048      // W2 transpose: (MEMD/32)*(HID/32)
#define PREP_HX_CTAS    128       // hx: (HID/256)*BS
#define PREP_SMALL_CTAS (PREP_TRAN_CTAS + PREP_HX_CTAS)
#define PREP_CONV_CTAS  65536     // memory fp32->fp16: 256 thr x 8 elems = 2048/CTA

// ---------------- device scratch (static, no allocations) ----------------
__device__ __half g_memh[(long)MTOT * MEMD];   // fp16 copy of memory (256 MB, bss)
__device__ __half g_W2Th[HID * MEMD];          // W2 transposed fp16: [h][d], K-major
__device__ float  g_hx[BS * HID];              // x@W1 + b1 + b2
// logit partials: [N-block][wn-warp][row] — one writer per slot, deterministic
__device__ float  g_logitsp[4][4][MTOT];
__device__ float4 g_ctxp[SCH][BS][MEMD / 4];   // context partials, 4 MB

// ---------------- helpers ----------------
__device__ __forceinline__ uint32_t smem_u32(const void* p) {
    uint32_t a;
    asm("{ .reg .u64 t; cvta.to.shared.u64 t, %1; cvt.u32.u64 %0, t; }" : "=r"(a) : "l"(p));
    return a;
}
#define CP_ASYNC16(dst, src) \
    asm volatile("cp.async.cg.shared.global [%0], [%1], 16;" :: "r"(dst), "l"(src) : "memory")
#define CP_COMMIT() asm volatile("cp.async.commit_group;" ::: "memory")
#define CP_WAIT0()  asm volatile("cp.async.wait_group 0;" ::: "memory")

// ldmatrix x4: four 8x8 b16 tiles (native fp16 use)
#define LDSM4(r, addr) \
    asm volatile("ldmatrix.sync.aligned.m8n8.x4.shared.b16 {%0,%1,%2,%3}, [%4];" \
        : "=r"((r)[0]), "=r"((r)[1]), "=r"((r)[2]), "=r"((r)[3]) : "r"(addr))

// fp16 MMA, fp32 accumulate: m16n8k16
__device__ __forceinline__ void mma_f16(float* c, const uint32_t* a, const uint32_t* b) {
    asm volatile(
        "mma.sync.aligned.m16n8k16.row.col.f32.f16.f16.f32 "
        "{%0,%1,%2,%3}, {%4,%5,%6,%7}, {%8,%9}, {%0,%1,%2,%3};"
        : "+f"(c[0]), "+f"(c[1]), "+f"(c[2]), "+f"(c[3])
        : "r"(a[0]), "r"(a[1]), "r"(a[2]), "r"(a[3]), "r"(b[0]), "r"(b[1]));
}

__device__ __forceinline__ float fast_tanh(float x) {
    float t; asm("tanh.approx.f32 %0, %1;" : "=f"(t) : "f"(x));
    return t;
}

__device__ __forceinline__ uint32_t pack_h2(float a, float b) {
    __half2 h = __floats2half2_rn(a, b);
    return *(uint32_t*)&h;
}

// ============================================================
// Prep kernel: one launch, three independent jobs partitioned by blockIdx.x.
// Compute-bound jobs (transpose, hx) go FIRST so they overlap the convert
// stream's early waves; the final wave is pure bandwidth-bound convert.
// ============================================================
__global__ void __launch_bounds__(256) prep_kernel(
    const float4* __restrict__ mem4, const float* __restrict__ W2,
    const float* __restrict__ x, const float* __restrict__ W1,
    const float* __restrict__ b1, const float* __restrict__ b2)
{
    const int cta = blockIdx.x;
    const int tid = threadIdx.x;

    if (cta < PREP_TRAN_CTAS) {
        // ---- W2 transpose: 32x32 tile per CTA, threads act as (32, 8) ----
        __shared__ float t[32][33];
        const int d0 = (cta % (MEMD / 32)) * 32;
        const int h0 = (cta / (MEMD / 32)) * 32;
        const int tx = tid & 31, ty = tid >> 5;
        #pragma unroll
        for (int i = 0; i < 32; i += 8)
            t[ty + i][tx] = W2[(long)(d0 + ty + i) * HID + h0 + tx];
        __syncthreads();
        #pragma unroll
        for (int i = 0; i < 32; i += 8)
            g_W2Th[(long)(h0 + ty + i) * MEMD + d0 + tx] = __float2half(t[tx][ty + i]);
    } else if (cta < PREP_SMALL_CTAS) {
        // ---- hx: h = x@W1 + b1 + b2 ----
        const int c = cta - PREP_TRAN_CTAS;       // 0..127
        const int h = (c & 3) * 256 + tid;
        const int b = c >> 2;
        const float* xr = x + b * IND;
        float acc = 0.f;
        #pragma unroll 8
        for (int d = 0; d < IND; d++)
            acc += xr[d] * W1[(long)d * HID + h];
        g_hx[b * HID + h] = acc + b1[h] + b2[h];
    } else {
        // ---- memory fp32 -> fp16: each thread converts 8 floats ----
        long i = (long)(cta - PREP_SMALL_CTAS) * 256 + tid;   // uint4 slot
        float4 f0 = mem4[2 * i], f1 = mem4[2 * i + 1];
        uint4 v;
        v.x = pack_h2(f0.x, f0.y);
        v.y = pack_h2(f0.z, f0.w);
        v.z = pack_h2(f1.x, f1.y);
        v.w = pack_h2(f1.z, f1.w);
        ((uint4*)g_memh)[i] = v;
    }
}

// ============================================================
// Half-stage loader: A [128 x 64] + B [256 x 64] fp16, 128-B rows, swizzled
// row layout: 8 chunks of 16 B (8 fp16), chunk index XOR (row & 7)
// ============================================================
__device__ __forceinline__ void load_half(
    int tid, uint32_t st,
    const __half* __restrict__ Ag, const __half* __restrict__ Bg)
{
    #pragma unroll
    for (int o = tid; o < TM * 8; o += 256) {
        int r = o >> 3, ch = o & 7;
        uint32_t dst = st + (uint32_t)(r * 128 + ((ch ^ (r & 7)) << 4));
        CP_ASYNC16(dst, Ag + (long)r * MEMD + ch * 8);
    }
    #pragma unroll
    for (int o = tid; o < TN * 8; o += 256) {
        int r = o >> 3, ch = o & 7;
        uint32_t dst = st + HALF_A + (uint32_t)(r * 128 + ((ch ^ (r & 7)) << 4));
        CP_ASYNC16(dst, Bg + (long)r * MEMD + ch * 8);
    }
}

// ============================================================
// GEMM (memory @ W2T, fp16 -> fp32) fused with tanh/v-dot -> logit partials
// grid (HID/TN = 4, MTOT/TM = 512), 256 threads, warp tile 64x64
// ============================================================
__global__ void __launch_bounds__(256, 1) gemm_score_kernel(const float* __restrict__ v)
{
    extern __shared__ float dsm[];
    __shared__ float hxs[TN], vt[TN];

    const int tid  = threadIdx.x;
    const int wid  = tid >> 5, lane = tid & 31;
    const int wm   = wid >> 2, wn = wid & 3;       // 2 x 4 warp grid
    const int tg   = lane >> 2, tig = lane & 3;
    const int  nb  = blockIdx.x;                   // N-block id (0..3)
    const int  n0  = nb * TN;                      // global h base
    const long g0  = (long)blockIdx.y * TM;        // global row base
    const int  b   = blockIdx.y >> 4;              // SL/TM = 16 M-tiles per batch

    if (tid < TN) {
        hxs[tid] = g_hx[b * HID + n0 + tid];
        vt[tid]  = v[n0 + tid];
    }

    const uint32_t sbase = smem_u32(dsm);
    const __half* Ag = g_memh + g0 * MEMD;
    const __half* Bg = g_W2Th + (long)n0 * MEMD;

    // ldmatrix per-thread address pieces (identical per 64-K half)
    const int lane7 = lane & 7;
    const uint32_t rowA0 = (uint32_t)((wm * 64 + ((lane >> 3) & 1) * 8 + lane7) * 128);
    const uint32_t rowB0 = (uint32_t)((wn * 64 + ((lane >> 4) & 1) * 8 + lane7) * 128);
    const int cbA = (lane >> 4) & 1, cbB = (lane >> 3) & 1;
    uint32_t ofsA[4], ofsB[4];
    #pragma unroll
    for (int ks = 0; ks < 4; ks++) {               // 4 k16-steps per 64-K half
        ofsA[ks] = (uint32_t)(((2 * ks + cbA) ^ lane7) << 4);
        ofsB[ks] = (uint32_t)(((2 * ks + cbB) ^ lane7) << 4);
    }

    float acc[4][8][4];
    #pragma unroll
    for (int i = 0; i < 4; i++)
        #pragma unroll
        for (int j = 0; j < 8; j++)
            #pragma unroll
            for (int k = 0; k < 4; k++) acc[i][j][k] = 0.f;

    // prologue: stage 0 (both halves)
    load_half(tid, sbase,              Ag,      Bg);
    load_half(tid, sbase + HALF_BYTES, Ag + 64, Bg + 64);
    CP_COMMIT();

    for (int it = 0; it < NKITER; it++) {
        CP_WAIT0();
        __syncthreads();

        if (it + 1 < NKITER) {    // prefetch next stage into the other buffer
            uint32_t st = sbase + (uint32_t)((it + 1) & 1) * STG_BYTES;
            const __half* Ain = Ag + (it + 1) * KC;
            const __half* Bin = Bg + (it + 1) * KC;
            load_half(tid, st,              Ain,      Bin);
            load_half(tid, st + HALF_BYTES, Ain + 64, Bin + 64);
            CP_COMMIT();
        }

        const uint32_t stg = sbase + (uint32_t)(it & 1) * STG_BYTES;
        #pragma unroll
        for (int h = 0; h < 2; h++) {
            const uint32_t sA = stg + (uint32_t)h * HALF_BYTES;
            const uint32_t sB = sA + HALF_A;
            #pragma unroll
            for (int ks = 0; ks < 4; ks++) {       // each ks consumes K=16
                uint32_t a[4][4], bf[4][4];
                #pragma unroll
                for (int mi = 0; mi < 4; mi++)
                    LDSM4(a[mi], sA + rowA0 + (uint32_t)(mi * 2048) + ofsA[ks]);
                #pragma unroll
                for (int p = 0; p < 4; p++)        // each covers n16
                    LDSM4(bf[p], sB + rowB0 + (uint32_t)(p * 2048) + ofsB[ks]);
                #pragma unroll
                for (int mi = 0; mi < 4; mi++)
                    #pragma unroll
                    for (int p = 0; p < 4; p++) {
                        mma_f16(acc[mi][2 * p],     a[mi], &bf[p][0]);
                        mma_f16(acc[mi][2 * p + 1], a[mi], &bf[p][2]);
                    }
            }
        }
    }

    // Epilogue: partial logit over this warp's 64 h-columns; one writer per
    // (nb, wn, row) slot -> plain store, race-free, deterministic.
    #pragma unroll
    for (int mi = 0; mi < 4; mi++) {
        float p0 = 0.f, p1 = 0.f;
        #pragma unroll
        for (int ni = 0; ni < 8; ni++) {
            int col = wn * 64 + ni * 8 + tig * 2;
            float v0 = vt[col], v1 = vt[col + 1];
            float h0 = hxs[col], h1 = hxs[col + 1];
            p0 += v0 * fast_tanh(h0 + acc[mi][ni][0]) + v1 * fast_tanh(h1 + acc[mi][ni][1]);
            p1 += v0 * fast_tanh(h0 + acc[mi][ni][2]) + v1 * fast_tanh(h1 + acc[mi][ni][3]);
        }
        p0 += __shfl_xor_sync(0xFFFFFFFFu, p0, 1);
        p0 += __shfl_xor_sync(0xFFFFFFFFu, p0, 2);
        p1 += __shfl_xor_sync(0xFFFFFFFFu, p1, 1);
        p1 += __shfl_xor_sync(0xFFFFFFFFu, p1, 2);
        if (tig == 0) {
            long r = g0 + wm * 64 + mi * 16 + tg;
            g_logitsp[nb][wn][r]     = p0;
            g_logitsp[nb][wn][r + 8] = p1;
        }
    }
}

// ============================================================
// Softmax over summed logit partials
// ============================================================
__global__ void __launch_bounds__(256) softmax_kernel(float* __restrict__ out) {
    __shared__ float buf[SL];
    __shared__ float red[256];
    const int b = blockIdx.x, tid = threadIdx.x;
    const float* lp = &g_logitsp[0][0][0];
    float m = -1e30f;
    for (int s = tid; s < SL; s += 256) {
        int i = b * SL + s;
        float l = 0.f;
        #pragma unroll
        for (int j = 0; j < 16; j++)
            l += lp[j * MTOT + i];
        buf[s] = l;
        m = fmaxf(m, l);
    }
    red[tid] = m; __syncthreads();
    for (int o = 128; o > 0; o >>= 1) {
        if (tid < o) red[tid] = fmaxf(red[tid], red[tid + o]);
        __syncthreads();
    }
    m = red[0]; __syncthreads();
    float sum = 0.f;
    for (int s = tid; s < SL; s += 256) {
        float e = __expf(buf[s] - m);
        buf[s] = e;
        sum += e;
    }
    red[tid] = sum; __syncthreads();
    for (int o = 128; o > 0; o >>= 1) {
        if (tid < o) red[tid] += red[tid + o];
        __syncthreads();
    }
    float inv = 1.f / red[0];
    for (int s = tid; s < SL; s += 256)
        out[OUT_SCORE_OFF + b * SL + s] = buf[s] * inv;
}

// ============================================================
// Context partials from the fp16 memory copy: grid (SCH, BS), 256 threads.
// Unroll x4 with all four row-loads issued before consumption (MLP=4/thread),
// dual accumulator banks to keep FFMA chains short.
// ============================================================
__global__ void __launch_bounds__(256) context_partial_kernel(const float* __restrict__ out)
{
    const int sc = blockIdx.x, b = blockIdx.y;
    const int d8 = threadIdx.x;                       // 0..255
    const float* sp = out + OUT_SCORE_OFF + b * SL + sc * SROWS;
    const uint4* mb = (const uint4*)(g_memh + ((long)b * SL + sc * SROWS) * MEMD) + d8;
    float a0[8] = {0,0,0,0,0,0,0,0}, a1[8] = {0,0,0,0,0,0,0,0};

    #pragma unroll 1
    for (int s = 0; s < SROWS; s += 4) {
        // issue all 4 row loads + 4 score loads up front
        float w0 = sp[s], w1 = sp[s + 1], w2 = sp[s + 2], w3 = sp[s + 3];
        uint4 v0 = mb[(long)(s + 0) * (MEMD / 8)];
        uint4 v1 = mb[(long)(s + 1) * (MEMD / 8)];
        uint4 v2 = mb[(long)(s + 2) * (MEMD / 8)];
        uint4 v3 = mb[(long)(s + 3) * (MEMD / 8)];
        float2 f;
        f = __half22float2(*(__half2*)&v0.x); a0[0] += w0 * f.x; a0[1] += w0 * f.y;
        f = __half22float2(*(__half2*)&v0.y); a0[2] += w0 * f.x; a0[3] += w0 * f.y;
        f = __half22float2(*(__half2*)&v0.z); a0[4] += w0 * f.x; a0[5] += w0 * f.y;
        f = __half22float2(*(__half2*)&v0.w); a0[6] += w0 * f.x; a0[7] += w0 * f.y;
        f = __half22float2(*(__half2*)&v1.x); a1[0] += w1 * f.x; a1[1] += w1 * f.y;
        f = __half22float2(*(__half2*)&v1.y); a1[2] += w1 * f.x; a1[3] += w1 * f.y;
        f = __half22float2(*(__half2*)&v1.z); a1[4] += w1 * f.x; a1[5] += w1 * f.y;
        f = __half22float2(*(__half2*)&v1.w); a1[6] += w1 * f.x; a1[7] += w1 * f.y;
        f = __half22float2(*(__half2*)&v2.x); a0[0] += w2 * f.x; a0[1] += w2 * f.y;
        f = __half22float2(*(__half2*)&v2.y); a0[2] += w2 * f.x; a0[3] += w2 * f.y;
        f = __half22float2(*(__half2*)&v2.z); a0[4] += w2 * f.x; a0[5] += w2 * f.y;
        f = __half22float2(*(__half2*)&v2.w); a0[6] += w2 * f.x; a0[7] += w2 * f.y;
        f = __half22float2(*(__half2*)&v3.x); a1[0] += w3 * f.x; a1[1] += w3 * f.y;
        f = __half22float2(*(__half2*)&v3.y); a1[2] += w3 * f.x; a1[3] += w3 * f.y;
        f = __half22float2(*(__half2*)&v3.z); a1[4] += w3 * f.x; a1[5] += w3 * f.y;
        f = __half22float2(*(__half2*)&v3.w); a1[6] += w3 * f.x; a1[7] += w3 * f.y;
    }
    float4* dst = &g_ctxp[sc][b][2 * d8];
    dst[0] = make_float4(a0[0] + a1[0], a0[1] + a1[1], a0[2] + a1[2], a0[3] + a1[3]);
    dst[1] = make_float4(a0[4] + a1[4], a0[5] + a1[5], a0[6] + a1[6], a0[7] + a1[7]);
}

__global__ void __launch_bounds__(256) ctx_reduce_kernel(float* __restrict__ out) {
    const int i  = blockIdx.x * 256 + threadIdx.x;    // 0..16383 float4 slots
    const int b  = i / (MEMD / 4), d4 = i % (MEMD / 4);
    float4 s = make_float4(0.f, 0.f, 0.f, 0.f);
    #pragma unroll
    for (int c = 0; c < SCH; c++) {
        float4 p = g_ctxp[c][b][d4];
        s.x += p.x; s.y += p.y; s.z += p.z; s.w += p.w;
    }
    ((float4*)out)[i] = s;
}

// ============================================================
// Launch
// ============================================================
extern "C" void kernel_launch(void* const* d_in, const int* in_sizes, int n_in,
                              void* d_out, int out_size)
{
    const float* x      = (const float*)d_in[0];
    const float* memory = (const float*)d_in[1];
    const float* W1     = (const float*)d_in[2];
    const float* b1     = (const float*)d_in[3];
    const float* W2     = (const float*)d_in[4];
    const float* b2     = (const float*)d_in[5];
    const float* v      = (const float*)d_in[6];
    // d_in[7] = bv: cancels under softmax (shift invariance), unused.
    float* out = (float*)d_out;

    cudaFuncSetAttribute(gemm_score_kernel,
                         cudaFuncAttributeMaxDynamicSharedMemorySize, SMEM_GEMM);

    prep_kernel<<<PREP_SMALL_CTAS + PREP_CONV_CTAS, 256>>>(
        (const float4*)memory, W2, x, W1, b1, b2);
    gemm_score_kernel<<<dim3(HID / TN, MTOT / TM), 256, SMEM_GEMM>>>(v);
    softmax_kernel<<<BS, 256>>>(out);
    context_partial_kernel<<<dim3(SCH, BS), 256>>>(out);
    ctx_reduce_kernel<<<BS * MEMD / 4 / 256, 256>>>(out);
}